// round 14
// baseline (speedup 1.0000x reference)
#include <cuda_runtime.h>
#include <cstdint>

#define B_  64
#define C_  64
#define N_  1024
#define O_  128
#define K_  49
#define RT  16     // rows per CTA in knn kernel (= warps per CTA)
#define TB  512    // threads per CTA in knn kernel
#define NCH 8      // node chunks in projection kernel
#define NPC (N_/NCH)

#define INF_F __int_as_float(0x7f800000)
#define FULLM 0xffffffffu

// ---------------- scratch (device globals; no allocs allowed) ----------------
__device__ float g_Xt[B_*N_*C_];    // (b, n, c) node-major features
__device__ float g_Z [B_*N_*C_];    // (b, n, c) neighbor means
__device__ float g_part[B_*NCH*O_]; // partial relu-sums

// ---------------- f32x2 helpers (packed fp32 pair FMA, PTX-only) -------------
__device__ __forceinline__ unsigned long long pk2(float x) {
    unsigned long long r; unsigned u = __float_as_uint(x);
    asm("mov.b64 %0, {%1, %1};" : "=l"(r) : "r"(u));
    return r;
}
__device__ __forceinline__ unsigned long long fma2(unsigned long long a,
                                                   unsigned long long b,
                                                   unsigned long long c) {
    unsigned long long d;
    asm("fma.rn.f32x2 %0, %1, %2, %3;" : "=l"(d) : "l"(a), "l"(b), "l"(c));
    return d;
}
__device__ __forceinline__ unsigned long long add2(unsigned long long a,
                                                   unsigned long long b) {
    unsigned long long d;
    asm("add.rn.f32x2 %0, %1, %2;" : "=l"(d) : "l"(a), "l"(b));
    return d;
}
__device__ __forceinline__ float2 upk2(unsigned long long v) {
    unsigned lo, hi;
    asm("mov.b64 {%0, %1}, %2;" : "=r"(lo), "=r"(hi) : "l"(v));
    return make_float2(__uint_as_float(lo), __uint_as_float(hi));
}
__device__ __forceinline__ unsigned long long mk2(float lo, float hi) {
    unsigned long long r;
    asm("mov.b64 %0, {%1, %2};" : "=l"(r)
        : "r"(__float_as_uint(lo)), "r"(__float_as_uint(hi)));
    return r;
}

// ---------------- kernel A: transpose X (b,c,n) -> Xt (b,n,c) ----------------
__global__ void k_transpose(const float* __restrict__ X) {
    __shared__ float tile[32][33];
    const int b  = blockIdx.z;
    const int nb = blockIdx.x * 32;
    const int cb = blockIdx.y * 32;
    const int tx = threadIdx.x, ty = threadIdx.y;
    const float* Xb = X + (size_t)b * C_ * N_;
    #pragma unroll
    for (int i = ty; i < 32; i += 8)
        tile[i][tx] = Xb[(cb + i) * N_ + nb + tx];
    __syncthreads();
    float* Xtb = g_Xt + (size_t)b * N_ * C_;
    #pragma unroll
    for (int i = ty; i < 32; i += 8)
        Xtb[(nb + i) * C_ + cb + tx] = tile[tx][i];
}

// ---------------- kernel B: fused distance + top-49 select + aggregate -------
struct SmemB {
    float    xiT[C_][RT];     // transposed query rows: [c][r]
    float    sqi[RT];
    float    d2[RT][N_];      // squared distances (clamped >= 0, diag = inf)
    int      sel[RT][52];     // selected neighbor indices (49 used; also scratch)
    unsigned hist[RT][256];   // per-warp radix histogram
};

__global__ __launch_bounds__(TB) void k_knn(const float* __restrict__ X) {
    extern __shared__ char smem_raw[];
    SmemB& S = *reinterpret_cast<SmemB*>(smem_raw);

    const int b    = blockIdx.y;
    const int r0   = blockIdx.x * RT;
    const int tid  = threadIdx.x;
    const int lane = tid & 31;
    const int wid  = tid >> 5;        // 0..15

    const float* Xtb = g_Xt + (size_t)b * N_ * C_;

    // ---- load 16 query rows, transposed into [c][r] ----
    for (int i = tid; i < RT * C_; i += TB) {
        int r = i >> 6, c = i & 63;
        S.xiT[c][r] = Xtb[(r0 + r) * C_ + c];
    }
    __syncthreads();
    if (tid < RT) {
        float s = 0.f;
        #pragma unroll
        for (int c = 0; c < C_; c++) { float v = S.xiT[c][tid]; s = fmaf(v, v, s); }
        S.sqi[tid] = s;
    }
    __syncthreads();

    // ---- distance phase: d2[r][j] = |xi_r|^2 + |x_j|^2 - 2 xi_r . x_j ----
    // each thread handles j0 = tid and j1 = tid + 512, all 16 rows
    {
        const float* Xb = X + (size_t)b * C_ * N_;
        const int j0 = tid;
        unsigned long long dp[2][8];
        #pragma unroll
        for (int u = 0; u < 2; u++)
            #pragma unroll
            for (int q = 0; q < 8; q++) dp[u][q] = 0ull;
        float sq0 = 0.f, sq1 = 0.f;
        #pragma unroll
        for (int c = 0; c < C_; c++) {
            const float x0 = Xb[c * N_ + j0];
            const float x1 = Xb[c * N_ + j0 + 512];
            const unsigned long long x0p = pk2(x0), x1p = pk2(x1);
            sq0 = fmaf(x0, x0, sq0);
            sq1 = fmaf(x1, x1, sq1);
            const ulonglong2* xr = reinterpret_cast<const ulonglong2*>(&S.xiT[c][0]);
            #pragma unroll
            for (int q = 0; q < 4; q++) {
                ulonglong2 a = xr[q];
                dp[0][2*q]   = fma2(a.x, x0p, dp[0][2*q]);
                dp[0][2*q+1] = fma2(a.y, x0p, dp[0][2*q+1]);
                dp[1][2*q]   = fma2(a.x, x1p, dp[1][2*q]);
                dp[1][2*q+1] = fma2(a.y, x1p, dp[1][2*q+1]);
            }
        }
        #pragma unroll
        for (int u = 0; u < 2; u++) {
            const int   j   = j0 + u * 512;
            const float sqj = u ? sq1 : sq0;
            #pragma unroll
            for (int p = 0; p < 8; p++) {
                float2 dd = upk2(dp[u][p]);
                float d0 = fmaxf(S.sqi[2*p]   + sqj - 2.f * dd.x, 0.f);
                float d1 = fmaxf(S.sqi[2*p+1] + sqj - 2.f * dd.y, 0.f);
                if (j == r0 + 2*p)     d0 = INF_F;
                if (j == r0 + 2*p + 1) d1 = INF_F;
                S.d2[2*p][j]   = d0;
                S.d2[2*p+1][j] = d1;
            }
        }
    }
    __syncthreads();

    // ---- selection + aggregation: one warp per row, fully warp-local ----
    {
        const int r  = wid;
        const int jd = r0 + r;   // diagonal index (its key is inf)
        // lane holds keys for j = lane + 32*m  (monotone in (m, lane) -> j order)
        unsigned key[32];
        unsigned orv = 0u, andv = FULLM;
        #pragma unroll
        for (int m = 0; m < 32; m++) {
            const int j = lane + 32 * m;
            const unsigned k = __float_as_uint(S.d2[r][j]);
            key[m] = k;
            const bool d = (j == jd);
            orv  |= d ? 0u    : k;
            andv &= d ? FULLM : k;
        }
        // bounds of the 1023 finite keys (diag excluded)
        #pragma unroll
        for (int off = 16; off >= 1; off >>= 1) {
            orv  |= __shfl_xor_sync(FULLM, orv,  off);
            andv &= __shfl_xor_sync(FULLM, andv, off);
        }
        const int top = 31 - __clz((orv ^ andv) | 1u);
        const int sh  = (top >= 7) ? (top - 7) : 0;

        // histogram of finite keys over the 8-bit window [sh+7..sh]
        unsigned* hist = S.hist[r];
        *reinterpret_cast<uint4*>(&hist[lane * 8])     = make_uint4(0,0,0,0);
        *reinterpret_cast<uint4*>(&hist[lane * 8 + 4]) = make_uint4(0,0,0,0);
        __syncwarp();
        #pragma unroll
        for (int m = 0; m < 32; m++) {
            const int j = lane + 32 * m;
            if (j != jd) atomicAdd(&hist[(key[m] >> sh) & 255u], 1u);
        }
        __syncwarp();

        // scan the 256 bins; find the bin containing rank K
        const uint4 h0 = *reinterpret_cast<const uint4*>(&hist[lane * 8]);
        const uint4 h1 = *reinterpret_cast<const uint4*>(&hist[lane * 8 + 4]);
        unsigned c8[8] = {h0.x, h0.y, h0.z, h0.w, h1.x, h1.y, h1.z, h1.w};
        unsigned ssum = 0;
        #pragma unroll
        for (int i2 = 0; i2 < 8; i2++) ssum += c8[i2];
        unsigned incl = ssum;
        #pragma unroll
        for (int off = 1; off < 32; off <<= 1) {
            unsigned nv = __shfl_up_sync(FULLM, incl, off);
            if (lane >= off) incl += nv;
        }
        const unsigned excl = incl - ssum;
        const bool has = (excl < K_) && (K_ <= incl);
        const unsigned Lm = __ballot_sync(FULLM, has);
        const int L = __ffs(Lm) - 1;
        unsigned binv = 0, belowv = 0;
        if (lane == L) {
            unsigned run = excl;
            #pragma unroll
            for (int i2 = 0; i2 < 8; i2++) {
                if (run < K_ && K_ <= run + c8[i2]) { binv = lane * 8 + i2; belowv = run; }
                run += c8[i2];
            }
        }
        const unsigned bin   = __shfl_sync(FULLM, binv,   L);
        const unsigned below = __shfl_sync(FULLM, belowv, L);
        const unsigned cnt   = hist[bin];      // broadcast LDS

        const unsigned lanemask = (lane == 0) ? 0u : (FULLM >> (32 - lane));
        unsigned T, below_total;
        if (cnt <= 32) {
            // gather the bin's member keys into sel[] scratch (ballot compaction)
            int* cand = S.sel[r];
            unsigned bse = 0;
            #pragma unroll
            for (int m = 0; m < 32; m++) {
                const int j = lane + 32 * m;
                const bool me = (j != jd) && (((key[m] >> sh) & 255u) == bin);
                const unsigned msk = __ballot_sync(FULLM, me);
                if (me) cand[bse + __popc(msk & lanemask)] = (int)key[m];
                bse += __popc(msk);
            }
            __syncwarp();
            // exact in-bin rank: lane q ranks cand[q] among all members
            const unsigned mykey = (lane < (int)cnt) ? (unsigned)cand[lane] : FULLM;
            unsigned rlt = 0, rle = 0;
            for (unsigned q = 0; q < cnt; q++) {
                const unsigned kq = (unsigned)cand[q];
                rlt += (kq <  mykey);
                rle += (kq <= mykey);
            }
            const unsigned w2 = K_ - below;    // 1-based rank wanted inside bin
            const bool isT = (lane < (int)cnt) && (rlt < w2) && (w2 <= rle);
            const unsigned Tm = __ballot_sync(FULLM, isT);
            const int TL = __ffs(Tm) - 1;
            T = __shfl_sync(FULLM, mykey, TL);
            below_total = below + __shfl_sync(FULLM, rlt, TL);
            __syncwarp();                       // done reading cand scratch
        } else {
            // rare fallback (tie-heavy bin): binary search the low 'sh' bits
            const unsigned hi = (sh + 8 < 32) ? ((andv >> (sh + 8)) << (sh + 8)) : 0u;
            T = hi | (bin << sh);
            #pragma unroll 1
            for (int bit = sh - 1; bit >= 0; bit--) {
                const unsigned cnd = T | (1u << bit);
                unsigned c = 0;
                #pragma unroll
                for (int m = 0; m < 32; m++) c += (key[m] < cnd);
                c += __shfl_xor_sync(FULLM, c, 16);
                c += __shfl_xor_sync(FULLM, c, 8);
                c += __shfl_xor_sync(FULLM, c, 4);
                c += __shfl_xor_sync(FULLM, c, 2);
                c += __shfl_xor_sync(FULLM, c, 1);
                if (c < K_) T = cnd;
            }
            unsigned cb = 0;
            #pragma unroll
            for (int m = 0; m < 32; m++) cb += (key[m] < T);
            cb += __shfl_xor_sync(FULLM, cb, 16);
            cb += __shfl_xor_sync(FULLM, cb, 8);
            cb += __shfl_xor_sync(FULLM, cb, 4);
            cb += __shfl_xor_sync(FULLM, cb, 2);
            cb += __shfl_xor_sync(FULLM, cb, 1);
            below_total = cb;
        }
        const unsigned need = K_ - below_total;  // ties == T kept, lowest j first

        // extraction in ascending j order
        int* sel = S.sel[r];
        unsigned base = 0, tie_taken = 0;
        #pragma unroll
        for (int m = 0; m < 32; m++) {
            const unsigned k  = key[m];
            const bool lt = (k < T), eq = (k == T);
            const unsigned mlt = __ballot_sync(FULLM, lt);
            const unsigned meq = __ballot_sync(FULLM, eq);
            if (lt) sel[base + __popc(mlt & lanemask)] = lane + 32 * m;
            if (eq) {
                const unsigned rk = tie_taken + __popc(meq & lanemask);
                if (rk < need) sel[below_total + rk] = lane + 32 * m;
            }
            base      += __popc(mlt);
            tie_taken += __popc(meq);
        }
        __syncwarp();

        // ---- warp-local aggregation: z[r][c] = mean of 49 neighbor rows ----
        float acc0 = 0.f, acc1 = 0.f;
        #pragma unroll 7
        for (int k = 0; k < K_; k++) {
            const int j = sel[k];                  // LDS broadcast
            const float* xp = Xtb + j * C_;
            acc0 += xp[lane];
            acc1 += xp[lane + 32];
        }
        const float inv_k = 1.0f / (float)K_;
        float* zp = g_Z + ((size_t)b * N_ + r0 + r) * C_;
        zp[lane]      = acc0 * inv_k;
        zp[lane + 32] = acc1 * inv_k;
    }
}

// ---------------- kernel C: projection + ReLU + node-sum (f32x2) -------------
__global__ __launch_bounds__(O_) void k_proj(const float* __restrict__ W,
                                             const float* __restrict__ bias) {
    const int b  = blockIdx.y;
    const int ch = blockIdx.x;
    const int o  = threadIdx.x;

    unsigned long long w2[32];   // 32 packed pairs = 64 weights
    #pragma unroll
    for (int q = 0; q < 32; q++)
        w2[q] = mk2(W[o * C_ + 2*q], W[o * C_ + 2*q + 1]);
    const float bi = bias[o];

    __shared__ float4 s_z[8 * 16];   // 8 nodes x 64 floats
    const float4* Z4 =
        reinterpret_cast<const float4*>(g_Z + ((size_t)b * N_ + ch * NPC) * C_);

    float acc = 0.f;
    #pragma unroll 1
    for (int n0 = 0; n0 < NPC; n0 += 8) {
        s_z[o] = Z4[n0 * 16 + o];    // 128 float4 = 8 nodes
        __syncthreads();
        #pragma unroll
        for (int v = 0; v < 8; v++) {
            // z2[q] (q=0..15) = channel pairs {2q, 2q+1}; split q=0..7 / 8..15
            const ulonglong2* z2 = reinterpret_cast<const ulonglong2*>(&s_z[v * 16]);
            unsigned long long d0 = 0ull, d1 = 0ull, d2 = 0ull, d3 = 0ull;
            #pragma unroll
            for (int q = 0; q < 8; q++) {
                const ulonglong2 z  = z2[q];      // pairs 2q, 2q+1
                const ulonglong2 z5 = z2[q + 8];  // pairs 2q+16, 2q+17
                d0 = fma2(w2[2*q],      z.x,  d0);
                d1 = fma2(w2[2*q + 1],  z.y,  d1);
                d2 = fma2(w2[2*q + 16], z5.x, d2);
                d3 = fma2(w2[2*q + 17], z5.y, d3);
            }
            const unsigned long long dt = add2(add2(d0, d1), add2(d2, d3));
            const float2 dd = upk2(dt);
            acc += fmaxf(dd.x + dd.y + bi, 0.f);
        }
        __syncthreads();
    }
    g_part[((size_t)b * NCH + ch) * O_ + o] = acc;
}

// ---------------- kernel D: reduce chunks + BatchNorm affine ------------------
__global__ void k_final(const float* __restrict__ gamma,
                        const float* __restrict__ beta,
                        const float* __restrict__ rmean,
                        const float* __restrict__ rvar,
                        float* __restrict__ out) {
    const int i = blockIdx.x * 128 + threadIdx.x;  // 8192
    const int o = i & 127;
    const int b = i >> 7;
    float s = 0.f;
    #pragma unroll
    for (int ch = 0; ch < NCH; ch++) s += g_part[((size_t)b * NCH + ch) * O_ + o];
    const float m   = s * (1.0f / (float)N_);
    const float inv = rsqrtf(rvar[o] + 1e-5f);
    out[i] = gamma[o] * (m - rmean[o]) * inv + beta[o];
}

// ---------------- launch -----------------------------------------------------
extern "C" void kernel_launch(void* const* d_in, const int* in_sizes, int n_in,
                              void* d_out, int out_size) {
    (void)in_sizes; (void)n_in; (void)out_size;
    const float* X     = (const float*)d_in[0];
    const float* W     = (const float*)d_in[1];
    const float* bias  = (const float*)d_in[2];
    const float* gamma = (const float*)d_in[3];
    const float* beta  = (const float*)d_in[4];
    const float* rmean = (const float*)d_in[5];
    const float* rvar  = (const float*)d_in[6];
    float* out = (float*)d_out;

    dim3 gA(N_ / 32, C_ / 32, B_), bA(32, 8);
    k_transpose<<<gA, bA>>>(X);

    const int smemB = (int)sizeof(SmemB);
    cudaFuncSetAttribute(k_knn, cudaFuncAttributeMaxDynamicSharedMemorySize, smemB);
    k_knn<<<dim3(N_ / RT, B_), TB, smemB>>>(X);

    k_proj<<<dim3(NCH, B_), O_>>>(W, bias);
    k_final<<<B_ * O_ / 128, 128>>>(gamma, beta, rmean, rvar, out);
}

// round 16
// speedup vs baseline: 1.6150x; 1.6150x over previous
#include <cuda_runtime.h>
#include <cstdint>

#define B_  64
#define C_  64
#define N_  1024
#define O_  128
#define K_  49
#define RT  16     // rows per CTA in knn kernel (= warps per CTA)
#define TB  512    // threads per CTA in knn kernel
#define NCH 8      // node chunks in projection kernel
#define NPC (N_/NCH)

#define INF_F __int_as_float(0x7f800000)
#define FULLM 0xffffffffu

// ---------------- scratch (device globals; no allocs allowed) ----------------
__device__ float g_Xt[B_*N_*C_];    // (b, n, c) node-major features
__device__ float g_Z [B_*N_*C_];    // (b, n, c) neighbor means
__device__ float g_part[B_*NCH*O_]; // partial relu-sums

// ---------------- f32x2 helpers (packed fp32 pair FMA, PTX-only) -------------
__device__ __forceinline__ unsigned long long pk2(float x) {
    unsigned long long r; unsigned u = __float_as_uint(x);
    asm("mov.b64 %0, {%1, %1};" : "=l"(r) : "r"(u));
    return r;
}
__device__ __forceinline__ unsigned long long fma2(unsigned long long a,
                                                   unsigned long long b,
                                                   unsigned long long c) {
    unsigned long long d;
    asm("fma.rn.f32x2 %0, %1, %2, %3;" : "=l"(d) : "l"(a), "l"(b), "l"(c));
    return d;
}
__device__ __forceinline__ float2 upk2(unsigned long long v) {
    unsigned lo, hi;
    asm("mov.b64 {%0, %1}, %2;" : "=r"(lo), "=r"(hi) : "l"(v));
    return make_float2(__uint_as_float(lo), __uint_as_float(hi));
}

// ---------------- kernel A: transpose X (b,c,n) -> Xt (b,n,c) ----------------
__global__ void k_transpose(const float* __restrict__ X) {
    __shared__ float tile[32][33];
    const int b  = blockIdx.z;
    const int nb = blockIdx.x * 32;
    const int cb = blockIdx.y * 32;
    const int tx = threadIdx.x, ty = threadIdx.y;
    const float* Xb = X + (size_t)b * C_ * N_;
    #pragma unroll
    for (int i = ty; i < 32; i += 8)
        tile[i][tx] = Xb[(cb + i) * N_ + nb + tx];
    __syncthreads();
    float* Xtb = g_Xt + (size_t)b * N_ * C_;
    #pragma unroll
    for (int i = ty; i < 32; i += 8)
        Xtb[(nb + i) * C_ + cb + tx] = tile[tx][i];
}

// ---------------- kernel B: fused distance + top-49 select + aggregate -------
struct SmemB {
    float    xiT[C_][RT];     // transposed query rows: [c][r]
    float    sqi[RT];
    float    d2[RT][N_];      // squared distances (clamped >= 0, diag = inf)
    int      sel[RT][52];     // selected neighbor indices (49 used; also scratch)
    unsigned hist[RT][256];   // per-warp radix histogram
};

__global__ __launch_bounds__(TB) void k_knn(const float* __restrict__ X) {
    extern __shared__ char smem_raw[];
    SmemB& S = *reinterpret_cast<SmemB*>(smem_raw);

    const int b    = blockIdx.y;
    const int r0   = blockIdx.x * RT;
    const int tid  = threadIdx.x;
    const int lane = tid & 31;
    const int wid  = tid >> 5;        // 0..15

    const float* Xtb = g_Xt + (size_t)b * N_ * C_;

    // ---- load 16 query rows, transposed into [c][r] ----
    for (int i = tid; i < RT * C_; i += TB) {
        int r = i >> 6, c = i & 63;
        S.xiT[c][r] = Xtb[(r0 + r) * C_ + c];
    }
    __syncthreads();
    if (tid < RT) {
        float s = 0.f;
        #pragma unroll
        for (int c = 0; c < C_; c++) { float v = S.xiT[c][tid]; s = fmaf(v, v, s); }
        S.sqi[tid] = s;
    }
    __syncthreads();

    // ---- distance phase: d2[r][j] = |xi_r|^2 + |x_j|^2 - 2 xi_r . x_j ----
    // each thread handles j0 = tid and j1 = tid + 512, all 16 rows
    {
        const float* Xb = X + (size_t)b * C_ * N_;
        const int j0 = tid;
        unsigned long long dp[2][8];
        #pragma unroll
        for (int u = 0; u < 2; u++)
            #pragma unroll
            for (int q = 0; q < 8; q++) dp[u][q] = 0ull;
        float sq0 = 0.f, sq1 = 0.f;
        #pragma unroll
        for (int c = 0; c < C_; c++) {
            const float x0 = Xb[c * N_ + j0];
            const float x1 = Xb[c * N_ + j0 + 512];
            const unsigned long long x0p = pk2(x0), x1p = pk2(x1);
            sq0 = fmaf(x0, x0, sq0);
            sq1 = fmaf(x1, x1, sq1);
            const ulonglong2* xr = reinterpret_cast<const ulonglong2*>(&S.xiT[c][0]);
            #pragma unroll
            for (int q = 0; q < 4; q++) {
                ulonglong2 a = xr[q];
                dp[0][2*q]   = fma2(a.x, x0p, dp[0][2*q]);
                dp[0][2*q+1] = fma2(a.y, x0p, dp[0][2*q+1]);
                dp[1][2*q]   = fma2(a.x, x1p, dp[1][2*q]);
                dp[1][2*q+1] = fma2(a.y, x1p, dp[1][2*q+1]);
            }
        }
        #pragma unroll
        for (int u = 0; u < 2; u++) {
            const int   j   = j0 + u * 512;
            const float sqj = u ? sq1 : sq0;
            #pragma unroll
            for (int p = 0; p < 8; p++) {
                float2 dd = upk2(dp[u][p]);
                float d0 = fmaxf(S.sqi[2*p]   + sqj - 2.f * dd.x, 0.f);
                float d1 = fmaxf(S.sqi[2*p+1] + sqj - 2.f * dd.y, 0.f);
                if (j == r0 + 2*p)     d0 = INF_F;
                if (j == r0 + 2*p + 1) d1 = INF_F;
                S.d2[2*p][j]   = d0;
                S.d2[2*p+1][j] = d1;
            }
        }
    }
    __syncthreads();

    // ---- selection phase: one warp per row, exact top-49 (radix histogram) ----
    {
        const int r  = wid;
        const int jd = r0 + r;   // diagonal index (its key is inf)
        // lane holds keys for j = lane + 32*m  (monotone in (m, lane) -> j order)
        unsigned key[32];
        unsigned orv = 0u, andv = FULLM;
        #pragma unroll
        for (int m = 0; m < 32; m++) {
            const int j = lane + 32 * m;
            const unsigned k = __float_as_uint(S.d2[r][j]);
            key[m] = k;
            const bool d = (j == jd);
            orv  |= d ? 0u    : k;
            andv &= d ? FULLM : k;
        }
        // bounds of the 1023 finite keys (diag excluded)
        #pragma unroll
        for (int off = 16; off >= 1; off >>= 1) {
            orv  |= __shfl_xor_sync(FULLM, orv,  off);
            andv &= __shfl_xor_sync(FULLM, andv, off);
        }
        const int top = 31 - __clz((orv ^ andv) | 1u);
        const int sh  = (top >= 7) ? (top - 7) : 0;

        // histogram of finite keys over the 8-bit window [sh+7..sh]
        unsigned* hist = S.hist[r];
        *reinterpret_cast<uint4*>(&hist[lane * 8])     = make_uint4(0,0,0,0);
        *reinterpret_cast<uint4*>(&hist[lane * 8 + 4]) = make_uint4(0,0,0,0);
        __syncwarp();
        #pragma unroll
        for (int m = 0; m < 32; m++) {
            const int j = lane + 32 * m;
            if (j != jd) atomicAdd(&hist[(key[m] >> sh) & 255u], 1u);
        }
        __syncwarp();

        // scan the 256 bins; find the bin containing rank K
        const uint4 h0 = *reinterpret_cast<const uint4*>(&hist[lane * 8]);
        const uint4 h1 = *reinterpret_cast<const uint4*>(&hist[lane * 8 + 4]);
        unsigned c8[8] = {h0.x, h0.y, h0.z, h0.w, h1.x, h1.y, h1.z, h1.w};
        unsigned ssum = 0;
        #pragma unroll
        for (int i2 = 0; i2 < 8; i2++) ssum += c8[i2];
        unsigned incl = ssum;
        #pragma unroll
        for (int off = 1; off < 32; off <<= 1) {
            unsigned nv = __shfl_up_sync(FULLM, incl, off);
            if (lane >= off) incl += nv;
        }
        const unsigned excl = incl - ssum;
        const bool has = (excl < K_) && (K_ <= incl);
        const unsigned Lm = __ballot_sync(FULLM, has);
        const int L = __ffs(Lm) - 1;
        unsigned binv = 0, belowv = 0;
        if (lane == L) {
            unsigned run = excl;
            #pragma unroll
            for (int i2 = 0; i2 < 8; i2++) {
                if (run < K_ && K_ <= run + c8[i2]) { binv = lane * 8 + i2; belowv = run; }
                run += c8[i2];
            }
        }
        const unsigned bin   = __shfl_sync(FULLM, binv,   L);
        const unsigned below = __shfl_sync(FULLM, belowv, L);
        const unsigned cnt   = hist[bin];      // broadcast LDS

        const unsigned lanemask = (lane == 0) ? 0u : (FULLM >> (32 - lane));
        unsigned T, below_total;
        if (cnt <= 32) {
            // gather the bin's member keys into sel[] scratch (ballot compaction)
            int* cand = S.sel[r];
            unsigned bse = 0;
            #pragma unroll
            for (int m = 0; m < 32; m++) {
                const int j = lane + 32 * m;
                const bool me = (j != jd) && (((key[m] >> sh) & 255u) == bin);
                const unsigned msk = __ballot_sync(FULLM, me);
                if (me) cand[bse + __popc(msk & lanemask)] = (int)key[m];
                bse += __popc(msk);
            }
            __syncwarp();
            // exact in-bin rank: lane q ranks cand[q] among all members
            const unsigned mykey = (lane < (int)cnt) ? (unsigned)cand[lane] : FULLM;
            unsigned rlt = 0, rle = 0;
            for (unsigned q = 0; q < cnt; q++) {
                const unsigned kq = (unsigned)cand[q];
                rlt += (kq <  mykey);
                rle += (kq <= mykey);
            }
            const unsigned w2 = K_ - below;    // 1-based rank wanted inside bin
            const bool isT = (lane < (int)cnt) && (rlt < w2) && (w2 <= rle);
            const unsigned Tm = __ballot_sync(FULLM, isT);
            const int TL = __ffs(Tm) - 1;
            T = __shfl_sync(FULLM, mykey, TL);
            below_total = below + __shfl_sync(FULLM, rlt, TL);
            __syncwarp();                       // done reading cand scratch
        } else {
            // rare fallback (tie-heavy bin): binary search the low 'sh' bits
            const unsigned hi = (sh + 8 < 32) ? ((andv >> (sh + 8)) << (sh + 8)) : 0u;
            T = hi | (bin << sh);
            #pragma unroll 1
            for (int bit = sh - 1; bit >= 0; bit--) {
                const unsigned cnd = T | (1u << bit);
                unsigned c = 0;
                #pragma unroll
                for (int m = 0; m < 32; m++) c += (key[m] < cnd);
                c += __shfl_xor_sync(FULLM, c, 16);
                c += __shfl_xor_sync(FULLM, c, 8);
                c += __shfl_xor_sync(FULLM, c, 4);
                c += __shfl_xor_sync(FULLM, c, 2);
                c += __shfl_xor_sync(FULLM, c, 1);
                if (c < K_) T = cnd;
            }
            unsigned cb = 0;
            #pragma unroll
            for (int m = 0; m < 32; m++) cb += (key[m] < T);
            cb += __shfl_xor_sync(FULLM, cb, 16);
            cb += __shfl_xor_sync(FULLM, cb, 8);
            cb += __shfl_xor_sync(FULLM, cb, 4);
            cb += __shfl_xor_sync(FULLM, cb, 2);
            cb += __shfl_xor_sync(FULLM, cb, 1);
            below_total = cb;
        }
        const unsigned need = K_ - below_total;  // ties == T kept, lowest j first

        // extraction in ascending j order
        int* sel = S.sel[r];
        unsigned base = 0, tie_taken = 0;
        #pragma unroll
        for (int m = 0; m < 32; m++) {
            const unsigned k  = key[m];
            const bool lt = (k < T), eq = (k == T);
            const unsigned mlt = __ballot_sync(FULLM, lt);
            const unsigned meq = __ballot_sync(FULLM, eq);
            if (lt) sel[base + __popc(mlt & lanemask)] = lane + 32 * m;
            if (eq) {
                const unsigned rk = tie_taken + __popc(meq & lanemask);
                if (rk < need) sel[below_total + rk] = lane + 32 * m;
            }
            base      += __popc(mlt);
            tie_taken += __popc(meq);
        }
    }
    __syncthreads();

    // ---- aggregation phase: z[r][c] = mean over 49 neighbors of Xt[j][c] ----
    {
        const int c = tid & 63, g = tid >> 6;   // 8 groups of 64 threads
        const float inv_k = 1.0f / (float)K_;
        #pragma unroll 1
        for (int r = g; r < RT; r += 8) {
            float acc = 0.f;
            #pragma unroll
            for (int k = 0; k < K_; k++) {
                const int j = S.sel[r][k];
                acc += Xtb[j * C_ + c];
            }
            g_Z[((size_t)b * N_ + r0 + r) * C_ + c] = acc * inv_k;
        }
    }
}

// ---------------- kernel C: projection + ReLU + node-sum ----------------------
__global__ __launch_bounds__(O_) void k_proj(const float* __restrict__ W,
                                             const float* __restrict__ bias) {
    const int b  = blockIdx.y;
    const int ch = blockIdx.x;
    const int o  = threadIdx.x;

    float w[C_];
    #pragma unroll
    for (int c = 0; c < C_; c++) w[c] = W[o * C_ + c];
    const float bi = bias[o];

    __shared__ float4 s_z[8 * 16];   // 8 nodes x 64 floats
    const float4* Z4 =
        reinterpret_cast<const float4*>(g_Z + ((size_t)b * N_ + ch * NPC) * C_);

    float acc = 0.f;
    #pragma unroll 1
    for (int n0 = 0; n0 < NPC; n0 += 8) {
        s_z[o] = Z4[n0 * 16 + o];    // 128 float4 = 8 nodes
        __syncthreads();
        #pragma unroll
        for (int v = 0; v < 8; v++) {
            float d = 0.f;
            #pragma unroll
            for (int q = 0; q < 16; q++) {
                const float4 z = s_z[v * 16 + q];
                d = fmaf(w[4*q+0], z.x, d);
                d = fmaf(w[4*q+1], z.y, d);
                d = fmaf(w[4*q+2], z.z, d);
                d = fmaf(w[4*q+3], z.w, d);
            }
            acc += fmaxf(d + bi, 0.f);
        }
        __syncthreads();
    }
    g_part[((size_t)b * NCH + ch) * O_ + o] = acc;
}

// ---------------- kernel D: reduce chunks + BatchNorm affine ------------------
__global__ void k_final(const float* __restrict__ gamma,
                        const float* __restrict__ beta,
                        const float* __restrict__ rmean,
                        const float* __restrict__ rvar,
                        float* __restrict__ out) {
    const int i = blockIdx.x * 128 + threadIdx.x;  // 8192
    const int o = i & 127;
    const int b = i >> 7;
    float s = 0.f;
    #pragma unroll
    for (int ch = 0; ch < NCH; ch++) s += g_part[((size_t)b * NCH + ch) * O_ + o];
    const float m   = s * (1.0f / (float)N_);
    const float inv = rsqrtf(rvar[o] + 1e-5f);
    out[i] = gamma[o] * (m - rmean[o]) * inv + beta[o];
}

// ---------------- launch -----------------------------------------------------
extern "C" void kernel_launch(void* const* d_in, const int* in_sizes, int n_in,
                              void* d_out, int out_size) {
    (void)in_sizes; (void)n_in; (void)out_size;
    const float* X     = (const float*)d_in[0];
    const float* W     = (const float*)d_in[1];
    const float* bias  = (const float*)d_in[2];
    const float* gamma = (const float*)d_in[3];
    const float* beta  = (const float*)d_in[4];
    const float* rmean = (const float*)d_in[5];
    const float* rvar  = (const float*)d_in[6];
    float* out = (float*)d_out;

    dim3 gA(N_ / 32, C_ / 32, B_), bA(32, 8);
    k_transpose<<<gA, bA>>>(X);

    const int smemB = (int)sizeof(SmemB);
    cudaFuncSetAttribute(k_knn, cudaFuncAttributeMaxDynamicSharedMemorySize, smemB);
    k_knn<<<dim3(N_ / RT, B_), TB, smemB>>>(X);

    k_proj<<<dim3(NCH, B_), O_>>>(W, bias);
    k_final<<<B_ * O_ / 128, 128>>>(gamma, beta, rmean, rvar, out);
}

// round 17
// speedup vs baseline: 1.6614x; 1.0287x over previous
#include <cuda_runtime.h>
#include <cstdint>

#define B_  64
#define C_  64
#define N_  1024
#define O_  128
#define K_  49
#define RT  16     // rows per CTA in knn kernel (= warps per CTA)
#define TB  512    // threads per CTA in knn kernel
#define NCH 8      // node chunks in projection kernel
#define NPC (N_/NCH)

#define INF_F __int_as_float(0x7f800000)
#define FULLM 0xffffffffu

// ---------------- scratch (device globals; no allocs allowed) ----------------
__device__ float g_Xt[B_*N_*C_];    // (b, n, c) node-major features
__device__ float g_Z [B_*N_*C_];    // (b, n, c) neighbor means
__device__ float g_part[B_*NCH*O_]; // partial relu-sums

// ---------------- f32x2 helpers (packed fp32 pair FMA, PTX-only) -------------
__device__ __forceinline__ unsigned long long pk2(float x) {
    unsigned long long r; unsigned u = __float_as_uint(x);
    asm("mov.b64 %0, {%1, %1};" : "=l"(r) : "r"(u));
    return r;
}
__device__ __forceinline__ unsigned long long fma2(unsigned long long a,
                                                   unsigned long long b,
                                                   unsigned long long c) {
    unsigned long long d;
    asm("fma.rn.f32x2 %0, %1, %2, %3;" : "=l"(d) : "l"(a), "l"(b), "l"(c));
    return d;
}
__device__ __forceinline__ unsigned long long add2(unsigned long long a,
                                                   unsigned long long b) {
    unsigned long long d;
    asm("add.rn.f32x2 %0, %1, %2;" : "=l"(d) : "l"(a), "l"(b));
    return d;
}
__device__ __forceinline__ float2 upk2(unsigned long long v) {
    unsigned lo, hi;
    asm("mov.b64 {%0, %1}, %2;" : "=r"(lo), "=r"(hi) : "l"(v));
    return make_float2(__uint_as_float(lo), __uint_as_float(hi));
}
__device__ __forceinline__ unsigned long long mk2(float lo, float hi) {
    unsigned long long r;
    asm("mov.b64 %0, {%1, %2};" : "=l"(r)
        : "r"(__float_as_uint(lo)), "r"(__float_as_uint(hi)));
    return r;
}

// ---------------- kernel A: transpose X (b,c,n) -> Xt (b,n,c) ----------------
__global__ void k_transpose(const float* __restrict__ X) {
    __shared__ float tile[32][33];
    const int b  = blockIdx.z;
    const int nb = blockIdx.x * 32;
    const int cb = blockIdx.y * 32;
    const int tx = threadIdx.x, ty = threadIdx.y;
    const float* Xb = X + (size_t)b * C_ * N_;
    #pragma unroll
    for (int i = ty; i < 32; i += 8)
        tile[i][tx] = Xb[(cb + i) * N_ + nb + tx];
    __syncthreads();
    float* Xtb = g_Xt + (size_t)b * N_ * C_;
    #pragma unroll
    for (int i = ty; i < 32; i += 8)
        Xtb[(nb + i) * C_ + cb + tx] = tile[tx][i];
}

// ---------------- kernel B: fused distance + top-49 select + aggregate -------
struct SmemB {
    float    xiT[C_][RT];     // transposed query rows: [c][r]
    float    sqi[RT];
    float    d2[RT][N_];      // squared distances (clamped >= 0, diag = inf)
    int      sel[RT][52];     // selected neighbor indices (49 used; also scratch)
    unsigned hist[RT][256];   // per-warp radix histogram
};

__global__ __launch_bounds__(TB) void k_knn(const float* __restrict__ X) {
    extern __shared__ char smem_raw[];
    SmemB& S = *reinterpret_cast<SmemB*>(smem_raw);

    const int b    = blockIdx.y;
    const int r0   = blockIdx.x * RT;
    const int tid  = threadIdx.x;
    const int lane = tid & 31;
    const int wid  = tid >> 5;        // 0..15

    const float* Xtb = g_Xt + (size_t)b * N_ * C_;

    // ---- load 16 query rows, transposed into [c][r] ----
    for (int i = tid; i < RT * C_; i += TB) {
        int r = i >> 6, c = i & 63;
        S.xiT[c][r] = Xtb[(r0 + r) * C_ + c];
    }
    __syncthreads();
    if (tid < RT) {
        float s = 0.f;
        #pragma unroll
        for (int c = 0; c < C_; c++) { float v = S.xiT[c][tid]; s = fmaf(v, v, s); }
        S.sqi[tid] = s;
    }
    __syncthreads();

    // ---- distance phase: d2[r][j] = |xi_r|^2 + |x_j|^2 - 2 xi_r . x_j ----
    // each thread handles j0 = tid and j1 = tid + 512, all 16 rows
    {
        const float* Xb = X + (size_t)b * C_ * N_;
        const int j0 = tid;
        unsigned long long dp[2][8];
        #pragma unroll
        for (int u = 0; u < 2; u++)
            #pragma unroll
            for (int q = 0; q < 8; q++) dp[u][q] = 0ull;
        float sq0 = 0.f, sq1 = 0.f;
        #pragma unroll
        for (int c = 0; c < C_; c++) {
            const float x0 = Xb[c * N_ + j0];
            const float x1 = Xb[c * N_ + j0 + 512];
            const unsigned long long x0p = pk2(x0), x1p = pk2(x1);
            sq0 = fmaf(x0, x0, sq0);
            sq1 = fmaf(x1, x1, sq1);
            const ulonglong2* xr = reinterpret_cast<const ulonglong2*>(&S.xiT[c][0]);
            #pragma unroll
            for (int q = 0; q < 4; q++) {
                ulonglong2 a = xr[q];
                dp[0][2*q]   = fma2(a.x, x0p, dp[0][2*q]);
                dp[0][2*q+1] = fma2(a.y, x0p, dp[0][2*q+1]);
                dp[1][2*q]   = fma2(a.x, x1p, dp[1][2*q]);
                dp[1][2*q+1] = fma2(a.y, x1p, dp[1][2*q+1]);
            }
        }
        #pragma unroll
        for (int u = 0; u < 2; u++) {
            const int   j   = j0 + u * 512;
            const float sqj = u ? sq1 : sq0;
            #pragma unroll
            for (int p = 0; p < 8; p++) {
                float2 dd = upk2(dp[u][p]);
                float d0 = fmaxf(S.sqi[2*p]   + sqj - 2.f * dd.x, 0.f);
                float d1 = fmaxf(S.sqi[2*p+1] + sqj - 2.f * dd.y, 0.f);
                if (j == r0 + 2*p)     d0 = INF_F;
                if (j == r0 + 2*p + 1) d1 = INF_F;
                S.d2[2*p][j]   = d0;
                S.d2[2*p+1][j] = d1;
            }
        }
    }
    __syncthreads();

    // ---- selection phase: one warp per row, exact top-49 (radix histogram) ----
    {
        const int r  = wid;
        const int jd = r0 + r;   // diagonal index (its key is inf)
        // lane holds keys for j = lane + 32*m  (monotone in (m, lane) -> j order)
        unsigned key[32];
        unsigned orv = 0u, andv = FULLM;
        #pragma unroll
        for (int m = 0; m < 32; m++) {
            const int j = lane + 32 * m;
            const unsigned k = __float_as_uint(S.d2[r][j]);
            key[m] = k;
            const bool d = (j == jd);
            orv  |= d ? 0u    : k;
            andv &= d ? FULLM : k;
        }
        // bounds of the 1023 finite keys (diag excluded)
        #pragma unroll
        for (int off = 16; off >= 1; off >>= 1) {
            orv  |= __shfl_xor_sync(FULLM, orv,  off);
            andv &= __shfl_xor_sync(FULLM, andv, off);
        }
        const int top = 31 - __clz((orv ^ andv) | 1u);
        const int sh  = (top >= 7) ? (top - 7) : 0;

        // histogram of finite keys over the 8-bit window [sh+7..sh]
        unsigned* hist = S.hist[r];
        *reinterpret_cast<uint4*>(&hist[lane * 8])     = make_uint4(0,0,0,0);
        *reinterpret_cast<uint4*>(&hist[lane * 8 + 4]) = make_uint4(0,0,0,0);
        __syncwarp();
        #pragma unroll
        for (int m = 0; m < 32; m++) {
            const int j = lane + 32 * m;
            if (j != jd) atomicAdd(&hist[(key[m] >> sh) & 255u], 1u);
        }
        __syncwarp();

        // scan the 256 bins; find the bin containing rank K
        const uint4 h0 = *reinterpret_cast<const uint4*>(&hist[lane * 8]);
        const uint4 h1 = *reinterpret_cast<const uint4*>(&hist[lane * 8 + 4]);
        unsigned c8[8] = {h0.x, h0.y, h0.z, h0.w, h1.x, h1.y, h1.z, h1.w};
        unsigned ssum = 0;
        #pragma unroll
        for (int i2 = 0; i2 < 8; i2++) ssum += c8[i2];
        unsigned incl = ssum;
        #pragma unroll
        for (int off = 1; off < 32; off <<= 1) {
            unsigned nv = __shfl_up_sync(FULLM, incl, off);
            if (lane >= off) incl += nv;
        }
        const unsigned excl = incl - ssum;
        const bool has = (excl < K_) && (K_ <= incl);
        const unsigned Lm = __ballot_sync(FULLM, has);
        const int L = __ffs(Lm) - 1;
        unsigned binv = 0, belowv = 0;
        if (lane == L) {
            unsigned run = excl;
            #pragma unroll
            for (int i2 = 0; i2 < 8; i2++) {
                if (run < K_ && K_ <= run + c8[i2]) { binv = lane * 8 + i2; belowv = run; }
                run += c8[i2];
            }
        }
        const unsigned bin   = __shfl_sync(FULLM, binv,   L);
        const unsigned below = __shfl_sync(FULLM, belowv, L);
        const unsigned cnt   = hist[bin];      // broadcast LDS

        const unsigned lanemask = (lane == 0) ? 0u : (FULLM >> (32 - lane));
        unsigned T, below_total;
        if (cnt <= 32) {
            // gather the bin's member keys into sel[] scratch (ballot compaction)
            int* cand = S.sel[r];
            unsigned bse = 0;
            #pragma unroll
            for (int m = 0; m < 32; m++) {
                const int j = lane + 32 * m;
                const bool me = (j != jd) && (((key[m] >> sh) & 255u) == bin);
                const unsigned msk = __ballot_sync(FULLM, me);
                if (me) cand[bse + __popc(msk & lanemask)] = (int)key[m];
                bse += __popc(msk);
            }
            __syncwarp();
            // exact in-bin rank: lane q ranks cand[q] among all members
            const unsigned mykey = (lane < (int)cnt) ? (unsigned)cand[lane] : FULLM;
            unsigned rlt = 0, rle = 0;
            for (unsigned q = 0; q < cnt; q++) {
                const unsigned kq = (unsigned)cand[q];
                rlt += (kq <  mykey);
                rle += (kq <= mykey);
            }
            const unsigned w2 = K_ - below;    // 1-based rank wanted inside bin
            const bool isT = (lane < (int)cnt) && (rlt < w2) && (w2 <= rle);
            const unsigned Tm = __ballot_sync(FULLM, isT);
            const int TL = __ffs(Tm) - 1;
            T = __shfl_sync(FULLM, mykey, TL);
            below_total = below + __shfl_sync(FULLM, rlt, TL);
            __syncwarp();                       // done reading cand scratch
        } else {
            // rare fallback (tie-heavy bin): binary search the low 'sh' bits
            const unsigned hi = (sh + 8 < 32) ? ((andv >> (sh + 8)) << (sh + 8)) : 0u;
            T = hi | (bin << sh);
            #pragma unroll 1
            for (int bit = sh - 1; bit >= 0; bit--) {
                const unsigned cnd = T | (1u << bit);
                unsigned c = 0;
                #pragma unroll
                for (int m = 0; m < 32; m++) c += (key[m] < cnd);
                c += __shfl_xor_sync(FULLM, c, 16);
                c += __shfl_xor_sync(FULLM, c, 8);
                c += __shfl_xor_sync(FULLM, c, 4);
                c += __shfl_xor_sync(FULLM, c, 2);
                c += __shfl_xor_sync(FULLM, c, 1);
                if (c < K_) T = cnd;
            }
            unsigned cb = 0;
            #pragma unroll
            for (int m = 0; m < 32; m++) cb += (key[m] < T);
            cb += __shfl_xor_sync(FULLM, cb, 16);
            cb += __shfl_xor_sync(FULLM, cb, 8);
            cb += __shfl_xor_sync(FULLM, cb, 4);
            cb += __shfl_xor_sync(FULLM, cb, 2);
            cb += __shfl_xor_sync(FULLM, cb, 1);
            below_total = cb;
        }
        const unsigned need = K_ - below_total;  // ties == T kept, lowest j first

        // extraction in ascending j order
        int* sel = S.sel[r];
        unsigned base = 0, tie_taken = 0;
        #pragma unroll
        for (int m = 0; m < 32; m++) {
            const unsigned k  = key[m];
            const bool lt = (k < T), eq = (k == T);
            const unsigned mlt = __ballot_sync(FULLM, lt);
            const unsigned meq = __ballot_sync(FULLM, eq);
            if (lt) sel[base + __popc(mlt & lanemask)] = lane + 32 * m;
            if (eq) {
                const unsigned rk = tie_taken + __popc(meq & lanemask);
                if (rk < need) sel[below_total + rk] = lane + 32 * m;
            }
            base      += __popc(mlt);
            tie_taken += __popc(meq);
        }
    }
    __syncthreads();

    // ---- aggregation phase: z[r][c] = mean over 49 neighbors of Xt[j][c] ----
    {
        const int c = tid & 63, g = tid >> 6;   // 8 groups of 64 threads
        const float inv_k = 1.0f / (float)K_;
        #pragma unroll 1
        for (int r = g; r < RT; r += 8) {
            float acc = 0.f;
            #pragma unroll
            for (int k = 0; k < K_; k++) {
                const int j = S.sel[r][k];
                acc += Xtb[j * C_ + c];
            }
            g_Z[((size_t)b * N_ + r0 + r) * C_ + c] = acc * inv_k;
        }
    }
}

// ---------------- kernel C: projection + ReLU + node-sum (f32x2) -------------
__global__ __launch_bounds__(O_) void k_proj(const float* __restrict__ W,
                                             const float* __restrict__ bias) {
    const int b  = blockIdx.y;
    const int ch = blockIdx.x;
    const int o  = threadIdx.x;

    // pack weights into 32 f32x2 pairs (w2[p] = channels {2p, 2p+1})
    unsigned long long w2[32];
    const float4* W4 = reinterpret_cast<const float4*>(W + o * C_);
    #pragma unroll
    for (int q = 0; q < 16; q++) {
        const float4 wv = W4[q];
        w2[2*q]     = mk2(wv.x, wv.y);
        w2[2*q + 1] = mk2(wv.z, wv.w);
    }
    const float bi = bias[o];

    __shared__ float4 s_z[8 * 16];   // 8 nodes x 64 floats
    const float4* Z4 =
        reinterpret_cast<const float4*>(g_Z + ((size_t)b * N_ + ch * NPC) * C_);

    float acc = 0.f;
    #pragma unroll 1
    for (int n0 = 0; n0 < NPC; n0 += 8) {
        s_z[o] = Z4[n0 * 16 + o];    // 128 float4 = 8 nodes
        __syncthreads();
        #pragma unroll
        for (int v = 0; v < 8; v++) {
            // z2[q] (q=0..15): .x = chan pair {4q,4q+1} (= w2[2q]),
            //                  .y = chan pair {4q+2,4q+3} (= w2[2q+1])
            const ulonglong2* z2 = reinterpret_cast<const ulonglong2*>(&s_z[v * 16]);
            unsigned long long d0 = 0ull, d1 = 0ull, d2 = 0ull, d3 = 0ull;
            #pragma unroll
            for (int q = 0; q < 8; q++) {
                const ulonglong2 za = z2[q];      // chans 4q..4q+3
                const ulonglong2 zb = z2[q + 8];  // chans 4q+32..4q+35
                d0 = fma2(w2[2*q],      za.x, d0);
                d1 = fma2(w2[2*q + 1],  za.y, d1);
                d2 = fma2(w2[2*q + 16], zb.x, d2);
                d3 = fma2(w2[2*q + 17], zb.y, d3);
            }
            const unsigned long long dt = add2(add2(d0, d1), add2(d2, d3));
            const float2 dd = upk2(dt);
            acc += fmaxf(dd.x + dd.y + bi, 0.f);
        }
        __syncthreads();
    }
    g_part[((size_t)b * NCH + ch) * O_ + o] = acc;
}

// ---------------- kernel D: reduce chunks + BatchNorm affine ------------------
__global__ void k_final(const float* __restrict__ gamma,
                        const float* __restrict__ beta,
                        const float* __restrict__ rmean,
                        const float* __restrict__ rvar,
                        float* __restrict__ out) {
    const int i = blockIdx.x * 128 + threadIdx.x;  // 8192
    const int o = i & 127;
    const int b = i >> 7;
    float s = 0.f;
    #pragma unroll
    for (int ch = 0; ch < NCH; ch++) s += g_part[((size_t)b * NCH + ch) * O_ + o];
    const float m   = s * (1.0f / (float)N_);
    const float inv = rsqrtf(rvar[o] + 1e-5f);
    out[i] = gamma[o] * (m - rmean[o]) * inv + beta[o];
}

// ---------------- launch -----------------------------------------------------
extern "C" void kernel_launch(void* const* d_in, const int* in_sizes, int n_in,
                              void* d_out, int out_size) {
    (void)in_sizes; (void)n_in; (void)out_size;
    const float* X     = (const float*)d_in[0];
    const float* W     = (const float*)d_in[1];
    const float* bias  = (const float*)d_in[2];
    const float* gamma = (const float*)d_in[3];
    const float* beta  = (const float*)d_in[4];
    const float* rmean = (const float*)d_in[5];
    const float* rvar  = (const float*)d_in[6];
    float* out = (float*)d_out;

    dim3 gA(N_ / 32, C_ / 32, B_), bA(32, 8);
    k_transpose<<<gA, bA>>>(X);

    const int smemB = (int)sizeof(SmemB);
    cudaFuncSetAttribute(k_knn, cudaFuncAttributeMaxDynamicSharedMemorySize, smemB);
    k_knn<<<dim3(N_ / RT, B_), TB, smemB>>>(X);

    k_proj<<<dim3(NCH, B_), O_>>>(W, bias);
    k_final<<<B_ * O_ / 128, 128>>>(gamma, beta, rmean, rvar, out);
}